// round 7
// baseline (speedup 1.0000x reference)
#include <cuda_runtime.h>
#include <math.h>

#define NN 6144
#define NV 3
#define NK 10
#define NF 512
#define YP 12
#define NITERS 2
#define BN_EPS 1e-5f

#define M_CHUNK 1024
#define MQP 260                        // 256 idx + pad; MQP % 8 == 4 -> conflict-free phases
#define NCHUNK (NN / M_CHUNK)          // 6
#define ITS_PER_CHUNK (M_CHUNK / 64)   // 16
#define NSTEPS (NN / 64)               // 96

// ---------------- scratch ----------------
__device__ float g_proj[NV * NN * YP];
__device__ float g_Y[NV * NN * YP];
__device__ float g_z[NN * YP];
__device__ float g_stats[NITERS * 2 * NK];
__device__ int   g_cnt[NITERS];

// ---------------- packed f32x2 helpers ----------------
__device__ __forceinline__ unsigned long long pack2(float a, float b) {
    unsigned long long r;
    asm("mov.b64 %0, {%1, %2};" : "=l"(r) : "f"(a), "f"(b));
    return r;
}
__device__ __forceinline__ void ffma2(unsigned long long& d, unsigned long long a, unsigned long long b) {
    asm("fma.rn.f32x2 %0, %1, %2, %0;" : "+l"(d) : "l"(a), "l"(b));
}
__device__ __forceinline__ float2 unpack2(unsigned long long v) {
    float2 r;
    asm("mov.b64 {%0, %1}, %2;" : "=f"(r.x), "=f"(r.y) : "l"(v));
    return r;
}

// ---------------- kernel 1: proj (also zeroes stats + counters) ----------------
__global__ __launch_bounds__(256) void proj_kernel(const float* __restrict__ feat,
                                                   const float* __restrict__ U) {
    __shared__ float Ut[NK][NF];
    int tid = threadIdx.x, lane = tid & 31, wid = tid >> 5;
    int bx = blockIdx.x;
    if (bx == 0) {
        if (tid < NITERS * 2 * NK) g_stats[tid] = 0.0f;
        if (tid >= 64 && tid < 64 + NITERS) g_cnt[tid - 64] = 0;
    }

    int v = bx / (NN / 8);
    int rb = bx % (NN / 8);

    for (int i = tid; i < NF * NK; i += 256) {
        int f = i / NK, k = i % NK;
        Ut[k][f] = U[(size_t)v * NF * NK + i];
    }
    __syncthreads();

    int n = rb * 8 + wid;
    const float4* xr = (const float4*)(feat + ((size_t)v * NN + n) * NF);
    float acc[NK];
#pragma unroll
    for (int k = 0; k < NK; k++) acc[k] = 0.0f;

#pragma unroll
    for (int it = 0; it < NF / 128; it++) {
        int f4 = it * 32 + lane;
        float4 x = xr[f4];
#pragma unroll
        for (int k = 0; k < NK; k++) {
            float4 u = *(const float4*)&Ut[k][f4 * 4];
            acc[k] = fmaf(x.x, u.x, acc[k]);
            acc[k] = fmaf(x.y, u.y, acc[k]);
            acc[k] = fmaf(x.z, u.z, acc[k]);
            acc[k] = fmaf(x.w, u.w, acc[k]);
        }
    }
#pragma unroll
    for (int k = 0; k < NK; k++)
        for (int s = 16; s; s >>= 1) acc[k] += __shfl_xor_sync(0xffffffffu, acc[k], s);

    if (lane == 0) {
        float* pr = g_proj + ((size_t)v * NN + n) * YP;
#pragma unroll
        for (int k = 0; k < NK; k++) pr[k] = acc[k];
    }
}

// ---------------- kernel 2: Y[v,n,k] = sum_m L[v,n,m] * z[m,k] ----------------
// 256 threads, 2 CTAs/SM, 8 rows/warp, LDG.64 (float2), depth-1 ping-pong.
// Per warp-step: 64 m-values (2/lane), z LDS amortized over 8 rows.
#define GEMV_THREADS 256
#define RPW 8
#define ROWS_PER_BLOCK 64     // 8 warps * 8 rows

__global__ __launch_bounds__(GEMV_THREADS, 2) void gemv_kernel(const float* __restrict__ lap,
                                                               const float* __restrict__ z_ext,
                                                               int use_ext) {
    const float* zsrc = use_ext ? z_ext : g_z;
    const int zstr = use_ext ? NK : YP;
    __shared__ unsigned long long zt[4 * 5 * MQP];   // 41,600 B

    int tid = threadIdx.x, lane = tid & 31, wid = tid >> 5;
    int bx = blockIdx.x;
    int v = bx / (NN / ROWS_PER_BLOCK);
    int rb = bx % (NN / ROWS_PER_BLOCK);
    int n0 = rb * ROWS_PER_BLOCK + wid * RPW;

    const float2* L2p = (const float2*)(lap + ((size_t)v * NN + n0) * (size_t)NN);
    const int ROW2 = NN / 2;

    unsigned long long acc[RPW][5];
#pragma unroll
    for (int r = 0; r < RPW; r++)
#pragma unroll
        for (int p = 0; p < 5; p++) acc[r][p] = 0ull;

    // lane handles m = step*64 + 2*lane, 2*lane+1
    // z smem layout: zt[(q*5+p)*MQP + (m>>2)], q = m&3
    int qe = 2 * (lane & 1);           // q of first elem of this lane's float2
    int idx0 = lane >> 1;              // m>>2 base within step's 64-m window
    // per-step idx advance: +16 (64 m / 4)

    float2 a[RPW], b[RPW];
#pragma unroll
    for (int r = 0; r < RPW; r++) a[r] = __ldcs(L2p + (size_t)r * ROW2 + lane);
#pragma unroll
    for (int r = 0; r < RPW; r++) b[r] = __ldcs(L2p + (size_t)r * ROW2 + 32 + lane);

    for (int c = 0; c < NCHUNK; c++) {
        __syncthreads();
        for (int i = tid; i < 5 * M_CHUNK; i += GEMV_THREADS) {
            int p = i >> 10;                  // 0..4
            int j = i & (M_CHUNK - 1);
            const float2* zp2 = (const float2*)(zsrc + (size_t)(c * M_CHUNK + j) * zstr + 2 * p);
            float2 zv = *zp2;
            zt[((j & 3) * 5 + p) * MQP + (j >> 2)] = pack2(zv.x, zv.y);
        }
        __syncthreads();

#pragma unroll 2
        for (int it = 0; it < ITS_PER_CHUNK; it++) {
            int s = c * ITS_PER_CHUNK + it;
            int sp = (s + 2 < NSTEPS) ? s + 2 : (NSTEPS - 1);
            // prefetch step s+2's L (front-batched LDG.64 x8)
            float2 nb[RPW];
#pragma unroll
            for (int r = 0; r < RPW; r++)
                nb[r] = __ldcs(L2p + (size_t)r * ROW2 + sp * 32 + lane);

            int mi = it * 16 + idx0;
            // first m (q = qe), second m (q = qe+1)
#pragma unroll
            for (int h = 0; h < 2; h++) {
                unsigned long long zq[5];
                int qb = (qe + h) * 5;
#pragma unroll
                for (int p = 0; p < 5; p++) zq[p] = zt[(qb + p) * MQP + mi];
#pragma unroll
                for (int r = 0; r < RPW; r++) {
                    float av = h ? a[r].y : a[r].x;
                    unsigned long long d = pack2(av, av);
#pragma unroll
                    for (int p = 0; p < 5; p++) ffma2(acc[r][p], d, zq[p]);
                }
            }
#pragma unroll
            for (int r = 0; r < RPW; r++) { a[r] = b[r]; b[r] = nb[r]; }
        }
    }

#pragma unroll
    for (int r = 0; r < RPW; r++) {
        float vals[NK];
#pragma unroll
        for (int p = 0; p < 5; p++) {
            float2 f = unpack2(acc[r][p]);
            vals[2 * p] = f.x;
            vals[2 * p + 1] = f.y;
        }
#pragma unroll
        for (int k = 0; k < NK; k++)
            for (int s = 16; s; s >>= 1) vals[k] += __shfl_xor_sync(0xffffffffu, vals[k], s);
        if (lane == 0) {
            float* yr = g_Y + ((size_t)v * NN + n0 + r) * YP;
#pragma unroll
            for (int k = 0; k < NK; k++) yr[k] = vals[k];
        }
    }
}

// ---------------- kernel 3: fused combine + BN + SELU ----------------
__device__ __forceinline__ float softplusf(float x) {
    return fmaxf(x, 0.0f) + __logf(1.0f + __expf(-fabsf(x)));
}

__device__ __forceinline__ void ds_comb(float* a1, const float* a2) {
    float S1 = 0.0f, S2 = 0.0f;
#pragma unroll
    for (int k = 0; k < NK; k++) { S1 += a1[k]; S2 += a2[k]; }
    float i1 = 1.0f / S1, i2 = 1.0f / S2;
    float u1 = (float)NK * i1, u2 = (float)NK * i2;
    float b1[NK], b2[NK];
    float sb1 = 0.0f, sb2 = 0.0f, dot = 0.0f;
#pragma unroll
    for (int k = 0; k < NK; k++) {
        b1[k] = (a1[k] - 1.0f) * i1;
        b2[k] = (a2[k] - 1.0f) * i2;
        sb1 += b1[k];
        sb2 += b2[k];
        dot += b1[k] * b2[k];
    }
    float C = sb1 * sb2 - dot;
    float invd = 1.0f / (1.0f - C);
    float Sn = (float)NK * (1.0f - C) / (u1 * u2);
#pragma unroll
    for (int k = 0; k < NK; k++)
        a1[k] = (b1[k] * b2[k] + b1[k] * u2 + b2[k] * u1) * invd * Sn + 1.0f;
}

__device__ __forceinline__ float seluf(float x) {
    const float sc = 1.0507009873554805f, al = 1.6732632423543772f;
    return x > 0.0f ? sc * x : sc * al * (__expf(x) - 1.0f);
}

#define CMB_THREADS 64
#define CMB_BLOCKS (NN / CMB_THREADS)   // 96 <= 148 -> co-resident, spin safe
__global__ __launch_bounds__(CMB_THREADS) void combine_bn_kernel(const float* __restrict__ z_ext,
                                                                 int use_ext, int t,
                                                                 float* __restrict__ out,
                                                                 const float* __restrict__ gamma,
                                                                 const float* __restrict__ beta,
                                                                 const float* __restrict__ theta) {
    const float* zsrc = use_ext ? z_ext : g_z;
    const int zstr = use_ext ? NK : YP;
    int n = blockIdx.x * CMB_THREADS + threadIdx.x;
    int lane = threadIdx.x & 31;

    float zn[NK];
#pragma unroll
    for (int p = 0; p < 5; p++) {
        float2 zv = *(const float2*)(zsrc + (size_t)n * zstr + 2 * p);
        zn[2 * p] = zv.x;
        zn[2 * p + 1] = zv.y;
    }

    float ac[NK];
#pragma unroll
    for (int v = 0; v < NV; v++) {
        const float4* y4 = (const float4*)(g_Y + ((size_t)v * NN + n) * YP);
        const float4* p4 = (const float4*)(g_proj + ((size_t)v * NN + n) * YP);
        float yv[12], pv[12];
#pragma unroll
        for (int q = 0; q < 3; q++) {
            float4 yq = y4[q];
            float4 pq = p4[q];
            yv[4 * q] = yq.x; yv[4 * q + 1] = yq.y; yv[4 * q + 2] = yq.z; yv[4 * q + 3] = yq.w;
            pv[4 * q] = pq.x; pv[4 * q + 1] = pq.y; pv[4 * q + 2] = pq.z; pv[4 * q + 3] = pq.w;
        }
        float av[NK];
#pragma unroll
        for (int k = 0; k < NK; k++) av[k] = softplusf(zn[k] - yv[k] + pv[k]) + 1.0f;
        if (v == 0) {
#pragma unroll
            for (int k = 0; k < NK; k++) ac[k] = av[k];
        } else {
            ds_comb(ac, av);
        }
    }

    float rs[NK], rq[NK];
#pragma unroll
    for (int k = 0; k < NK; k++) { rs[k] = ac[k]; rq[k] = ac[k] * ac[k]; }
#pragma unroll
    for (int k = 0; k < NK; k++) {
        for (int s = 16; s; s >>= 1) {
            rs[k] += __shfl_xor_sync(0xffffffffu, rs[k], s);
            rq[k] += __shfl_xor_sync(0xffffffffu, rq[k], s);
        }
    }
    __shared__ float sh[2 * NK];
    if (threadIdx.x < 2 * NK) sh[threadIdx.x] = 0.0f;
    __syncthreads();
    if (lane == 0) {
#pragma unroll
        for (int k = 0; k < NK; k++) {
            atomicAdd(&sh[k], rs[k]);
            atomicAdd(&sh[NK + k], rq[k]);
        }
    }
    __syncthreads();
    if (threadIdx.x < 2 * NK)
        atomicAdd(&g_stats[t * 2 * NK + threadIdx.x], sh[threadIdx.x]);

    __threadfence();
    __syncthreads();
    if (threadIdx.x == 0) {
        atomicAdd(&g_cnt[t], 1);
        while (atomicAdd(&g_cnt[t], 0) < CMB_BLOCKS) { __nanosleep(64); }
    }
    __syncthreads();
    __threadfence();

    float th = theta[0];
#pragma unroll
    for (int k = 0; k < NK; k++) {
        float mu = g_stats[t * 2 * NK + k] * (1.0f / NN);
        float ms = g_stats[t * 2 * NK + NK + k] * (1.0f / NN);
        float var = ms - mu * mu;
        float inv = rsqrtf(var + BN_EPS);
        float hn = (ac[k] - mu) * inv * gamma[k] + beta[k];
        float zz = seluf(hn - th) - seluf(-hn - th);
        out[(size_t)t * NN * NK + (size_t)n * NK + k] = zz;
        g_z[(size_t)n * YP + k] = zz;
    }
}

// ---------------- launcher ----------------
extern "C" void kernel_launch(void* const* d_in, const int* in_sizes, int n_in,
                              void* d_out, int out_size) {
    (void)in_sizes; (void)n_in; (void)out_size;
    const float* feat  = (const float*)d_in[0];
    const float* lap   = (const float*)d_in[1];
    const float* z0    = (const float*)d_in[2];
    const float* U     = (const float*)d_in[3];
    const float* theta = (const float*)d_in[4];
    const float* gamma = (const float*)d_in[5];
    const float* beta  = (const float*)d_in[6];
    float* out = (float*)d_out;

    proj_kernel<<<NV * (NN / 8), 256>>>(feat, U);

    for (int t = 0; t < NITERS; t++) {
        int use_ext = (t == 0) ? 1 : 0;
        gemv_kernel<<<NV * (NN / ROWS_PER_BLOCK), GEMV_THREADS>>>(lap, z0, use_ext);
        combine_bn_kernel<<<CMB_BLOCKS, CMB_THREADS>>>(z0, use_ext, t, out, gamma, beta, theta);
    }
}

// round 8
// speedup vs baseline: 3.2816x; 3.2816x over previous
#include <cuda_runtime.h>
#include <math.h>

#define NN 6144
#define NV 3
#define NK 10
#define NF 512
#define YP 12
#define NITERS 2
#define BN_EPS 1e-5f

#define M_CHUNK 1536
#define MQP 388                        // 384 + pad; MQP % 8 == 4 -> conflict-free
#define NCHUNK 4                       // 6144 / 1536
#define STEPS_PER_CHUNK 12
#define NSTEPS 48                      // 6144 / 128

// ---------------- scratch ----------------
__device__ float g_proj[NV * NN * YP];
__device__ float g_Y[NV * NN * YP];
__device__ float g_z[NN * YP];
__device__ float g_stats[NITERS * 2 * NK];
__device__ int   g_cnt[NITERS];

// ---------------- packed f32x2 helpers ----------------
__device__ __forceinline__ unsigned long long pack2(float a, float b) {
    unsigned long long r;
    asm("mov.b64 %0, {%1, %2};" : "=l"(r) : "f"(a), "f"(b));
    return r;
}
__device__ __forceinline__ void ffma2(unsigned long long& d, unsigned long long a, unsigned long long b) {
    asm("fma.rn.f32x2 %0, %1, %2, %0;" : "+l"(d) : "l"(a), "l"(b));
}
__device__ __forceinline__ float2 unpack2(unsigned long long v) {
    float2 r;
    asm("mov.b64 {%0, %1}, %2;" : "=f"(r.x), "=f"(r.y) : "l"(v));
    return r;
}

// ---------------- kernel 1: proj (also zeroes stats + counters) ----------------
__global__ __launch_bounds__(256) void proj_kernel(const float* __restrict__ feat,
                                                   const float* __restrict__ U) {
    __shared__ float Ut[NK][NF];
    int tid = threadIdx.x, lane = tid & 31, wid = tid >> 5;
    int bx = blockIdx.x;
    if (bx == 0) {
        if (tid < NITERS * 2 * NK) g_stats[tid] = 0.0f;
        if (tid >= 64 && tid < 64 + NITERS) g_cnt[tid - 64] = 0;
    }

    int v = bx / (NN / 8);
    int rb = bx % (NN / 8);

    for (int i = tid; i < NF * NK; i += 256) {
        int f = i / NK, k = i % NK;
        Ut[k][f] = U[(size_t)v * NF * NK + i];
    }
    __syncthreads();

    int n = rb * 8 + wid;
    const float4* xr = (const float4*)(feat + ((size_t)v * NN + n) * NF);
    float acc[NK];
#pragma unroll
    for (int k = 0; k < NK; k++) acc[k] = 0.0f;

#pragma unroll
    for (int it = 0; it < NF / 128; it++) {
        int f4 = it * 32 + lane;
        float4 x = xr[f4];
#pragma unroll
        for (int k = 0; k < NK; k++) {
            float4 u = *(const float4*)&Ut[k][f4 * 4];
            acc[k] = fmaf(x.x, u.x, acc[k]);
            acc[k] = fmaf(x.y, u.y, acc[k]);
            acc[k] = fmaf(x.z, u.z, acc[k]);
            acc[k] = fmaf(x.w, u.w, acc[k]);
        }
    }
#pragma unroll
    for (int k = 0; k < NK; k++)
        for (int s = 16; s; s >>= 1) acc[k] += __shfl_xor_sync(0xffffffffu, acc[k], s);

    if (lane == 0) {
        float* pr = g_proj + ((size_t)v * NN + n) * YP;
#pragma unroll
        for (int k = 0; k < NK; k++) pr[k] = acc[k];
    }
}

// ---------------- kernel 2: Y[v,n,k] = sum_m L[v,n,m] * z[m,k] ----------------
// 256 threads, 1 CTA/SM (no reg cap pressure), 8 rows/warp, LDG.128,
// triple-buffer +2-step register pipeline (16 LDG.128 in flight / warp = 8 KB).
#define GEMV_THREADS 256
#define RPW 8
#define ROWS_PER_BLOCK 64   // 8 warps * 8 rows

// one pipeline step: consume CONS (128 m-values), prefetch step s+2 into PRE
#define GSTEP(ITV, CONS, PRE)                                                   \
    do {                                                                        \
        int s_ = c * STEPS_PER_CHUNK + (ITV);                                   \
        int sp_ = (s_ + 2 < NSTEPS) ? s_ + 2 : NSTEPS - 1;                      \
        _Pragma("unroll")                                                       \
        for (int r = 0; r < RPW; r++)                                           \
            PRE[r] = __ldcs(L4 + (size_t)r * ROW4 + sp_ * 32 + lane);           \
        int mi_ = (ITV) * 32 + lane;                                            \
        _Pragma("unroll")                                                       \
        for (int q = 0; q < 4; q++) {                                           \
            unsigned long long zq[5];                                           \
            _Pragma("unroll")                                                   \
            for (int p = 0; p < 5; p++) zq[p] = zt[(q * 5 + p) * MQP + mi_];    \
            _Pragma("unroll")                                                   \
            for (int r = 0; r < RPW; r++) {                                     \
                float av_ = (q == 0) ? CONS[r].x : (q == 1) ? CONS[r].y         \
                           : (q == 2) ? CONS[r].z : CONS[r].w;                  \
                unsigned long long d_ = pack2(av_, av_);                        \
                _Pragma("unroll")                                               \
                for (int p = 0; p < 5; p++) ffma2(acc[r][p], d_, zq[p]);        \
            }                                                                   \
        }                                                                       \
    } while (0)

__global__ __launch_bounds__(GEMV_THREADS, 1) void gemv_kernel(const float* __restrict__ lap,
                                                               const float* __restrict__ z_ext,
                                                               int use_ext) {
    const float* zsrc = use_ext ? z_ext : g_z;
    const int zstr = use_ext ? NK : YP;
    extern __shared__ unsigned long long zt[];   // 4*5*MQP u64 = 62,080 B

    int tid = threadIdx.x, lane = tid & 31, wid = tid >> 5;
    int bx = blockIdx.x;
    int v = bx / (NN / ROWS_PER_BLOCK);
    int rb = bx % (NN / ROWS_PER_BLOCK);
    int n0 = rb * ROWS_PER_BLOCK + wid * RPW;

    const float4* L4 = (const float4*)(lap + ((size_t)v * NN + n0) * (size_t)NN);
    const int ROW4 = NN / 4;

    unsigned long long acc[RPW][5];
#pragma unroll
    for (int r = 0; r < RPW; r++)
#pragma unroll
        for (int p = 0; p < 5; p++) acc[r][p] = 0ull;

    float4 b0[RPW], b1[RPW], b2[RPW];
    // preload steps 0,1 (overlaps the first z fill)
#pragma unroll
    for (int r = 0; r < RPW; r++) b0[r] = __ldcs(L4 + (size_t)r * ROW4 + lane);
#pragma unroll
    for (int r = 0; r < RPW; r++) b1[r] = __ldcs(L4 + (size_t)r * ROW4 + 32 + lane);

    for (int c = 0; c < NCHUNK; c++) {
        __syncthreads();
#pragma unroll
        for (int p = 0; p < 5; p++) {
            for (int j = tid; j < M_CHUNK; j += GEMV_THREADS) {
                const float2* zp2 = (const float2*)(zsrc + (size_t)(c * M_CHUNK + j) * zstr + 2 * p);
                float2 zv = *zp2;
                zt[((j & 3) * 5 + p) * MQP + (j >> 2)] = pack2(zv.x, zv.y);
            }
        }
        __syncthreads();

        // 12 steps = 4 rotations of the 3-buffer pipeline (prefetch distance 2)
        for (int itb = 0; itb < STEPS_PER_CHUNK / 3; itb++) {
            GSTEP(itb * 3 + 0, b0, b2);
            GSTEP(itb * 3 + 1, b1, b0);
            GSTEP(itb * 3 + 2, b2, b1);
        }
    }

#pragma unroll
    for (int r = 0; r < RPW; r++) {
        float vals[NK];
#pragma unroll
        for (int p = 0; p < 5; p++) {
            float2 f = unpack2(acc[r][p]);
            vals[2 * p] = f.x;
            vals[2 * p + 1] = f.y;
        }
#pragma unroll
        for (int k = 0; k < NK; k++)
            for (int s = 16; s; s >>= 1) vals[k] += __shfl_xor_sync(0xffffffffu, vals[k], s);
        if (lane == 0) {
            float* yr = g_Y + ((size_t)v * NN + n0 + r) * YP;
#pragma unroll
            for (int k = 0; k < NK; k++) yr[k] = vals[k];
        }
    }
}

// ---------------- kernel 3: fused combine + BN + SELU ----------------
__device__ __forceinline__ float softplusf(float x) {
    return fmaxf(x, 0.0f) + __logf(1.0f + __expf(-fabsf(x)));
}

__device__ __forceinline__ void ds_comb(float* a1, const float* a2) {
    float S1 = 0.0f, S2 = 0.0f;
#pragma unroll
    for (int k = 0; k < NK; k++) { S1 += a1[k]; S2 += a2[k]; }
    float i1 = 1.0f / S1, i2 = 1.0f / S2;
    float u1 = (float)NK * i1, u2 = (float)NK * i2;
    float b1[NK], b2[NK];
    float sb1 = 0.0f, sb2 = 0.0f, dot = 0.0f;
#pragma unroll
    for (int k = 0; k < NK; k++) {
        b1[k] = (a1[k] - 1.0f) * i1;
        b2[k] = (a2[k] - 1.0f) * i2;
        sb1 += b1[k];
        sb2 += b2[k];
        dot += b1[k] * b2[k];
    }
    float C = sb1 * sb2 - dot;
    float invd = 1.0f / (1.0f - C);
    float Sn = (float)NK * (1.0f - C) / (u1 * u2);
#pragma unroll
    for (int k = 0; k < NK; k++)
        a1[k] = (b1[k] * b2[k] + b1[k] * u2 + b2[k] * u1) * invd * Sn + 1.0f;
}

__device__ __forceinline__ float seluf(float x) {
    const float sc = 1.0507009873554805f, al = 1.6732632423543772f;
    return x > 0.0f ? sc * x : sc * al * (__expf(x) - 1.0f);
}

#define CMB_THREADS 64
#define CMB_BLOCKS (NN / CMB_THREADS)   // 96 <= 148 -> co-resident, spin safe
__global__ __launch_bounds__(CMB_THREADS) void combine_bn_kernel(const float* __restrict__ z_ext,
                                                                 int use_ext, int t,
                                                                 float* __restrict__ out,
                                                                 const float* __restrict__ gamma,
                                                                 const float* __restrict__ beta,
                                                                 const float* __restrict__ theta) {
    const float* zsrc = use_ext ? z_ext : g_z;
    const int zstr = use_ext ? NK : YP;
    int n = blockIdx.x * CMB_THREADS + threadIdx.x;
    int lane = threadIdx.x & 31;

    float zn[NK];
#pragma unroll
    for (int p = 0; p < 5; p++) {
        float2 zv = *(const float2*)(zsrc + (size_t)n * zstr + 2 * p);
        zn[2 * p] = zv.x;
        zn[2 * p + 1] = zv.y;
    }

    float ac[NK];
#pragma unroll
    for (int v = 0; v < NV; v++) {
        const float4* y4 = (const float4*)(g_Y + ((size_t)v * NN + n) * YP);
        const float4* p4 = (const float4*)(g_proj + ((size_t)v * NN + n) * YP);
        float yv[12], pv[12];
#pragma unroll
        for (int q = 0; q < 3; q++) {
            float4 yq = y4[q];
            float4 pq = p4[q];
            yv[4 * q] = yq.x; yv[4 * q + 1] = yq.y; yv[4 * q + 2] = yq.z; yv[4 * q + 3] = yq.w;
            pv[4 * q] = pq.x; pv[4 * q + 1] = pq.y; pv[4 * q + 2] = pq.z; pv[4 * q + 3] = pq.w;
        }
        float av[NK];
#pragma unroll
        for (int k = 0; k < NK; k++) av[k] = softplusf(zn[k] - yv[k] + pv[k]) + 1.0f;
        if (v == 0) {
#pragma unroll
            for (int k = 0; k < NK; k++) ac[k] = av[k];
        } else {
            ds_comb(ac, av);
        }
    }

    float rs[NK], rq[NK];
#pragma unroll
    for (int k = 0; k < NK; k++) { rs[k] = ac[k]; rq[k] = ac[k] * ac[k]; }
#pragma unroll
    for (int k = 0; k < NK; k++) {
        for (int s = 16; s; s >>= 1) {
            rs[k] += __shfl_xor_sync(0xffffffffu, rs[k], s);
            rq[k] += __shfl_xor_sync(0xffffffffu, rq[k], s);
        }
    }
    __shared__ float sh[2 * NK];
    if (threadIdx.x < 2 * NK) sh[threadIdx.x] = 0.0f;
    __syncthreads();
    if (lane == 0) {
#pragma unroll
        for (int k = 0; k < NK; k++) {
            atomicAdd(&sh[k], rs[k]);
            atomicAdd(&sh[NK + k], rq[k]);
        }
    }
    __syncthreads();
    if (threadIdx.x < 2 * NK)
        atomicAdd(&g_stats[t * 2 * NK + threadIdx.x], sh[threadIdx.x]);

    __threadfence();
    __syncthreads();
    if (threadIdx.x == 0) {
        atomicAdd(&g_cnt[t], 1);
        while (atomicAdd(&g_cnt[t], 0) < CMB_BLOCKS) { __nanosleep(64); }
    }
    __syncthreads();
    __threadfence();

    float th = theta[0];
#pragma unroll
    for (int k = 0; k < NK; k++) {
        float mu = g_stats[t * 2 * NK + k] * (1.0f / NN);
        float ms = g_stats[t * 2 * NK + NK + k] * (1.0f / NN);
        float var = ms - mu * mu;
        float inv = rsqrtf(var + BN_EPS);
        float hn = (ac[k] - mu) * inv * gamma[k] + beta[k];
        float zz = seluf(hn - th) - seluf(-hn - th);
        out[(size_t)t * NN * NK + (size_t)n * NK + k] = zz;
        g_z[(size_t)n * YP + k] = zz;
    }
}

// ---------------- launcher ----------------
extern "C" void kernel_launch(void* const* d_in, const int* in_sizes, int n_in,
                              void* d_out, int out_size) {
    (void)in_sizes; (void)n_in; (void)out_size;
    const float* feat  = (const float*)d_in[0];
    const float* lap   = (const float*)d_in[1];
    const float* z0    = (const float*)d_in[2];
    const float* U     = (const float*)d_in[3];
    const float* theta = (const float*)d_in[4];
    const float* gamma = (const float*)d_in[5];
    const float* beta  = (const float*)d_in[6];
    float* out = (float*)d_out;

    const int ZT_BYTES = 4 * 5 * MQP * 8;   // 62,080 B dynamic smem
    static int configured = 0;
    if (!configured) {
        cudaFuncSetAttribute(gemv_kernel, cudaFuncAttributeMaxDynamicSharedMemorySize, ZT_BYTES);
        configured = 1;
    }

    proj_kernel<<<NV * (NN / 8), 256>>>(feat, U);

    for (int t = 0; t < NITERS; t++) {
        int use_ext = (t == 0) ? 1 : 0;
        gemv_kernel<<<NV * (NN / ROWS_PER_BLOCK), GEMV_THREADS, ZT_BYTES>>>(lap, z0, use_ext);
        combine_bn_kernel<<<CMB_BLOCKS, CMB_THREADS>>>(z0, use_ext, t, out, gamma, beta, theta);
    }
}

// round 10
// speedup vs baseline: 3.7538x; 1.1439x over previous
#include <cuda_runtime.h>
#include <math.h>

#define NN 6144
#define NV 3
#define NK 10
#define NF 512
#define YP 12
#define NITERS 2
#define BN_EPS 1e-5f

#define M_CHUNK 2048
#define MQP 514                        // 512 + pad
#define NCHUNK 3                       // 6144 / 2048
#define STEPS_PER_CHUNK 16             // 2048 / 128
#define NSTEPS 48                      // 6144 / 128

#define GEMV_THREADS 256
#define RPW 8
#define ROWS_PER_BLOCK 64
#define NTILES (NV * (NN / ROWS_PER_BLOCK))   // 288
#define CMB_NBLK (NN / GEMV_THREADS)          // 24

// ---------------- scratch ----------------
__device__ float g_proj[NV * NN * YP];
__device__ float g_Y[NV * NN * YP];
__device__ float g_z[NN * YP];
__device__ float g_stats[NITERS * 2 * NK];
__device__ int   g_sync[8];

// ---------------- packed f32x2 helpers ----------------
__device__ __forceinline__ unsigned long long pack2(float a, float b) {
    unsigned long long r;
    asm("mov.b64 %0, {%1, %2};" : "=l"(r) : "f"(a), "f"(b));
    return r;
}
__device__ __forceinline__ void ffma2(unsigned long long& d, unsigned long long a, unsigned long long b) {
    asm("fma.rn.f32x2 %0, %1, %2, %0;" : "+l"(d) : "l"(a), "l"(b));
}
__device__ __forceinline__ float2 unpack2(unsigned long long v) {
    float2 r;
    asm("mov.b64 {%0, %1}, %2;" : "=f"(r.x), "=f"(r.y) : "l"(v));
    return r;
}

// ---------------- kernel 1: proj (also zeroes stats + sync counters) ----------------
__global__ __launch_bounds__(256) void proj_kernel(const float* __restrict__ feat,
                                                   const float* __restrict__ U) {
    __shared__ float Ut[NK][NF];
    int tid = threadIdx.x, lane = tid & 31, wid = tid >> 5;
    int bx = blockIdx.x;
    if (bx == 0) {
        if (tid < NITERS * 2 * NK) g_stats[tid] = 0.0f;
        if (tid >= 64 && tid < 72) g_sync[tid - 64] = 0;
    }

    int v = bx / (NN / 8);
    int rb = bx % (NN / 8);

    for (int i = tid; i < NF * NK; i += 256) {
        int f = i / NK, k = i % NK;
        Ut[k][f] = U[(size_t)v * NF * NK + i];
    }
    __syncthreads();

    int n = rb * 8 + wid;
    const float4* xr = (const float4*)(feat + ((size_t)v * NN + n) * NF);
    float acc[NK];
#pragma unroll
    for (int k = 0; k < NK; k++) acc[k] = 0.0f;

#pragma unroll
    for (int it = 0; it < NF / 128; it++) {
        int f4 = it * 32 + lane;
        float4 x = xr[f4];
#pragma unroll
        for (int k = 0; k < NK; k++) {
            float4 u = *(const float4*)&Ut[k][f4 * 4];
            acc[k] = fmaf(x.x, u.x, acc[k]);
            acc[k] = fmaf(x.y, u.y, acc[k]);
            acc[k] = fmaf(x.z, u.z, acc[k]);
            acc[k] = fmaf(x.w, u.w, acc[k]);
        }
    }
#pragma unroll
    for (int k = 0; k < NK; k++)
        for (int s = 16; s; s >>= 1) acc[k] += __shfl_xor_sync(0xffffffffu, acc[k], s);

    if (lane == 0) {
        float* pr = g_proj + ((size_t)v * NN + n) * YP;
#pragma unroll
        for (int k = 0; k < NK; k++) pr[k] = acc[k];
    }
}

// ---------------- helpers for the fused phases ----------------
__device__ __forceinline__ float softplusf(float x) {
    return fmaxf(x, 0.0f) + __logf(1.0f + __expf(-fabsf(x)));
}

__device__ __forceinline__ void ds_comb(float* a1, const float* a2) {
    float S1 = 0.0f, S2 = 0.0f;
#pragma unroll
    for (int k = 0; k < NK; k++) { S1 += a1[k]; S2 += a2[k]; }
    float i1 = 1.0f / S1, i2 = 1.0f / S2;
    float u1 = (float)NK * i1, u2 = (float)NK * i2;
    float b1[NK], b2[NK];
    float sb1 = 0.0f, sb2 = 0.0f, dot = 0.0f;
#pragma unroll
    for (int k = 0; k < NK; k++) {
        b1[k] = (a1[k] - 1.0f) * i1;
        b2[k] = (a2[k] - 1.0f) * i2;
        sb1 += b1[k];
        sb2 += b2[k];
        dot += b1[k] * b2[k];
    }
    float C = sb1 * sb2 - dot;
    float invd = 1.0f / (1.0f - C);
    float Sn = (float)NK * (1.0f - C) / (u1 * u2);
#pragma unroll
    for (int k = 0; k < NK; k++)
        a1[k] = (b1[k] * b2[k] + b1[k] * u2 + b2[k] * u1) * invd * Sn + 1.0f;
}

__device__ __forceinline__ float seluf(float x) {
    const float sc = 1.0507009873554805f, al = 1.6732632423543772f;
    return x > 0.0f ? sc * x : sc * al * (__expf(x) - 1.0f);
}

// grid-wide sync: all CTAs co-resident (grid == #SMs, 1 CTA/SM)
__device__ __forceinline__ void gsync(int idx) {
    __syncthreads();
    __threadfence();
    if (threadIdx.x == 0) {
        atomicAdd(&g_sync[idx], 1);
        while (atomicAdd(&g_sync[idx], 0) < (int)gridDim.x) { __nanosleep(64); }
    }
    __syncthreads();
}

// ---------------- kernel 2: persistent fused iteration kernel ----------------
__global__ __launch_bounds__(GEMV_THREADS, 1) void persist_kernel(const float* __restrict__ lap,
                                                                  const float* __restrict__ z0,
                                                                  float* __restrict__ out,
                                                                  const float* __restrict__ gamma,
                                                                  const float* __restrict__ beta,
                                                                  const float* __restrict__ theta) {
    extern __shared__ unsigned long long zt[];   // 4*5*MQP u64 = 82,240 B

    int tid = threadIdx.x, lane = tid & 31, wid = tid >> 5;
    const int ROW4 = NN / 4;

#pragma unroll 1
    for (int t = 0; t < NITERS; t++) {
        const float* zsrc = (t == 0) ? z0 : g_z;
        const int zstr = (t == 0) ? NK : YP;

        // ---------- gemv phase: Y[v,n,:] = L_v[n,:] @ z ----------
#pragma unroll 1
        for (int tile = blockIdx.x; tile < NTILES; tile += gridDim.x) {
            int v = tile / (NN / ROWS_PER_BLOCK);
            int rb = tile % (NN / ROWS_PER_BLOCK);
            int n0 = rb * ROWS_PER_BLOCK + wid * RPW;

            const float4* L4 = (const float4*)(lap + ((size_t)v * NN + n0) * (size_t)NN);

            unsigned long long acc[RPW][5];
#pragma unroll
            for (int r = 0; r < RPW; r++)
#pragma unroll
                for (int p = 0; p < 5; p++) acc[r][p] = 0ull;

            float4 a[RPW], b[RPW], cb[RPW];
#pragma unroll
            for (int r = 0; r < RPW; r++) a[r] = __ldcs(L4 + (size_t)r * ROW4 + lane);
#pragma unroll
            for (int r = 0; r < RPW; r++) b[r] = __ldcs(L4 + (size_t)r * ROW4 + 32 + lane);

#pragma unroll 1
            for (int c = 0; c < NCHUNK; c++) {
                __syncthreads();
                for (int i = tid; i < 5 * M_CHUNK; i += GEMV_THREADS) {
                    int p = i >> 11;                  // 0..4
                    int j = i & (M_CHUNK - 1);
                    const float2* zp2 = (const float2*)(zsrc + (size_t)(c * M_CHUNK + j) * zstr + 2 * p);
                    float2 zv = *zp2;
                    zt[((j & 3) * 5 + p) * MQP + (j >> 2)] = pack2(zv.x, zv.y);
                }
                __syncthreads();

#pragma unroll 2
                for (int it = 0; it < STEPS_PER_CHUNK; it++) {
                    int s = c * STEPS_PER_CHUNK + it;
                    int sp = (s + 2 < NSTEPS) ? s + 2 : (NSTEPS - 1);
#pragma unroll
                    for (int r = 0; r < RPW; r++)
                        cb[r] = __ldcs(L4 + (size_t)r * ROW4 + sp * 32 + lane);

                    int mi = it * 32 + lane;
#pragma unroll
                    for (int q = 0; q < 4; q++) {
                        unsigned long long zq[5];
#pragma unroll
                        for (int p = 0; p < 5; p++) zq[p] = zt[(q * 5 + p) * MQP + mi];
#pragma unroll
                        for (int r = 0; r < RPW; r++) {
                            float av = (q == 0) ? a[r].x : (q == 1) ? a[r].y : (q == 2) ? a[r].z : a[r].w;
                            unsigned long long d = pack2(av, av);
#pragma unroll
                            for (int p = 0; p < 5; p++) ffma2(acc[r][p], d, zq[p]);
                        }
                    }
#pragma unroll
                    for (int r = 0; r < RPW; r++) { a[r] = b[r]; b[r] = cb[r]; }
                }
            }

#pragma unroll
            for (int r = 0; r < RPW; r++) {
                float vals[NK];
#pragma unroll
                for (int p = 0; p < 5; p++) {
                    float2 f = unpack2(acc[r][p]);
                    vals[2 * p] = f.x;
                    vals[2 * p + 1] = f.y;
                }
#pragma unroll
                for (int k = 0; k < NK; k++)
                    for (int s = 16; s; s >>= 1) vals[k] += __shfl_xor_sync(0xffffffffu, vals[k], s);
                if (lane == 0) {
                    float* yr = g_Y + ((size_t)v * NN + n0 + r) * YP;
#pragma unroll
                    for (int k = 0; k < NK; k++) yr[k] = vals[k];
                }
            }
            __syncthreads();
        }

        gsync(3 * t + 0);

        // ---------- combine phase (blocks 0..23 cover all n) ----------
        float hreg[NK];
        if (blockIdx.x < CMB_NBLK) {
            int n = blockIdx.x * GEMV_THREADS + tid;

            float zn[NK];
#pragma unroll
            for (int p = 0; p < 5; p++) {
                float2 zv = *(const float2*)(zsrc + (size_t)n * zstr + 2 * p);
                zn[2 * p] = zv.x;
                zn[2 * p + 1] = zv.y;
            }

#pragma unroll
            for (int v = 0; v < NV; v++) {
                const float4* y4 = (const float4*)(g_Y + ((size_t)v * NN + n) * YP);
                const float4* p4 = (const float4*)(g_proj + ((size_t)v * NN + n) * YP);
                float yv[12], pv[12];
#pragma unroll
                for (int q = 0; q < 3; q++) {
                    float4 yq = y4[q];
                    float4 pq = p4[q];
                    yv[4 * q] = yq.x; yv[4 * q + 1] = yq.y; yv[4 * q + 2] = yq.z; yv[4 * q + 3] = yq.w;
                    pv[4 * q] = pq.x; pv[4 * q + 1] = pq.y; pv[4 * q + 2] = pq.z; pv[4 * q + 3] = pq.w;
                }
                float av[NK];
#pragma unroll
                for (int k = 0; k < NK; k++) av[k] = softplusf(zn[k] - yv[k] + pv[k]) + 1.0f;
                if (v == 0) {
#pragma unroll
                    for (int k = 0; k < NK; k++) hreg[k] = av[k];
                } else {
                    ds_comb(hreg, av);
                }
            }

            float rs[NK], rq[NK];
#pragma unroll
            for (int k = 0; k < NK; k++) { rs[k] = hreg[k]; rq[k] = hreg[k] * hreg[k]; }
#pragma unroll
            for (int k = 0; k < NK; k++) {
                for (int s = 16; s; s >>= 1) {
                    rs[k] += __shfl_xor_sync(0xffffffffu, rs[k], s);
                    rq[k] += __shfl_xor_sync(0xffffffffu, rq[k], s);
                }
            }
            __shared__ float sh[2 * NK];
            if (tid < 2 * NK) sh[tid] = 0.0f;
            __syncthreads();
            if (lane == 0) {
#pragma unroll
                for (int k = 0; k < NK; k++) {
                    atomicAdd(&sh[k], rs[k]);
                    atomicAdd(&sh[NK + k], rq[k]);
                }
            }
            __syncthreads();
            if (tid < 2 * NK)
                atomicAdd(&g_stats[t * 2 * NK + tid], sh[tid]);
        }

        gsync(3 * t + 1);

        // ---------- BN + SELU phase ----------
        if (blockIdx.x < CMB_NBLK) {
            int n = blockIdx.x * GEMV_THREADS + tid;
            float th = theta[0];
#pragma unroll
            for (int k = 0; k < NK; k++) {
                float mu = g_stats[t * 2 * NK + k] * (1.0f / NN);
                float ms = g_stats[t * 2 * NK + NK + k] * (1.0f / NN);
                float var = ms - mu * mu;
                float inv = rsqrtf(var + BN_EPS);
                float hn = (hreg[k] - mu) * inv * gamma[k] + beta[k];
                float zz = seluf(hn - th) - seluf(-hn - th);
                out[(size_t)t * NN * NK + (size_t)n * NK + k] = zz;
                g_z[(size_t)n * YP + k] = zz;
            }
        }

        if (t + 1 < NITERS) gsync(3 * t + 2);   // g_z ready before next gemv
    }
}

// ---------------- launcher ----------------
extern "C" void kernel_launch(void* const* d_in, const int* in_sizes, int n_in,
                              void* d_out, int out_size) {
    (void)in_sizes; (void)n_in; (void)out_size;
    const float* feat  = (const float*)d_in[0];
    const float* lap   = (const float*)d_in[1];
    const float* z0    = (const float*)d_in[2];
    const float* U     = (const float*)d_in[3];
    const float* theta = (const float*)d_in[4];
    const float* gamma = (const float*)d_in[5];
    const float* beta  = (const float*)d_in[6];
    float* out = (float*)d_out;

    const int ZT_BYTES = 4 * 5 * MQP * 8;   // 82,240 B dynamic smem
    static int nsm = 0;
    if (nsm == 0) {
        cudaFuncSetAttribute(persist_kernel, cudaFuncAttributeMaxDynamicSharedMemorySize, ZT_BYTES);
        cudaDeviceGetAttribute(&nsm, cudaDevAttrMultiProcessorCount, 0);
        if (nsm <= 0) nsm = 148;
        if (nsm > NTILES) nsm = NTILES;
    }

    proj_kernel<<<NV * (NN / 8), 256>>>(feat, U);
    persist_kernel<<<nsm, GEMV_THREADS, ZT_BYTES>>>(lap, z0, out, gamma, beta, theta);
}

// round 11
// speedup vs baseline: 3.8822x; 1.0342x over previous
#include <cuda_runtime.h>
#include <math.h>

#define NN 6144
#define NV 3
#define NK 10
#define NF 512
#define YP 12
#define NITERS 2
#define BN_EPS 1e-5f

#define MSPLIT 3
#define M_CHUNK 2048                   // m per tile (one fill)
#define MQP 516                        // 512 + pad (u64 row stride)
#define STEPS 16                       // 2048 / 128

#define GEMV_THREADS 384               // 12 warps -> reg cap 170
#define RPW 8
#define ROWS_PER_BLOCK 96              // 12 warps * 8 rows
#define NRT (NN / ROWS_PER_BLOCK)      // 64 row-tiles per view
#define NTILES (MSPLIT * NV * NRT)     // 576

// ---------------- scratch ----------------
__device__ float g_proj[NV * NN * YP];
__device__ float g_Y[MSPLIT * NV * NN * YP];   // m-split partials
__device__ float g_z[NN * YP];
__device__ float g_stats[NITERS * 2 * NK];
__device__ int   g_cnt[NITERS];

// ---------------- packed f32x2 helpers ----------------
__device__ __forceinline__ unsigned long long pack2(float a, float b) {
    unsigned long long r;
    asm("mov.b64 %0, {%1, %2};" : "=l"(r) : "f"(a), "f"(b));
    return r;
}
__device__ __forceinline__ void ffma2(unsigned long long& d, unsigned long long a, unsigned long long b) {
    asm("fma.rn.f32x2 %0, %1, %2, %0;" : "+l"(d) : "l"(a), "l"(b));
}
__device__ __forceinline__ void fadd2(unsigned long long& d, unsigned long long a) {
    asm("add.rn.f32x2 %0, %0, %1;" : "+l"(d) : "l"(a));
}
__device__ __forceinline__ float2 unpack2(unsigned long long v) {
    float2 r;
    asm("mov.b64 {%0, %1}, %2;" : "=f"(r.x), "=f"(r.y) : "l"(v));
    return r;
}

// ---------------- kernel 1: proj (also zeroes stats + counters) ----------------
__global__ __launch_bounds__(256) void proj_kernel(const float* __restrict__ feat,
                                                   const float* __restrict__ U) {
    __shared__ float Ut[NK][NF];
    int tid = threadIdx.x, lane = tid & 31, wid = tid >> 5;
    int bx = blockIdx.x;
    if (bx == 0) {
        if (tid < NITERS * 2 * NK) g_stats[tid] = 0.0f;
        if (tid >= 64 && tid < 64 + NITERS) g_cnt[tid - 64] = 0;
    }

    int v = bx / (NN / 8);
    int rb = bx % (NN / 8);

    for (int i = tid; i < NF * NK; i += 256) {
        int f = i / NK, k = i % NK;
        Ut[k][f] = U[(size_t)v * NF * NK + i];
    }
    __syncthreads();

    int n = rb * 8 + wid;
    const float4* xr = (const float4*)(feat + ((size_t)v * NN + n) * NF);
    float acc[NK];
#pragma unroll
    for (int k = 0; k < NK; k++) acc[k] = 0.0f;

#pragma unroll
    for (int it = 0; it < NF / 128; it++) {
        int f4 = it * 32 + lane;
        float4 x = xr[f4];
#pragma unroll
        for (int k = 0; k < NK; k++) {
            float4 u = *(const float4*)&Ut[k][f4 * 4];
            acc[k] = fmaf(x.x, u.x, acc[k]);
            acc[k] = fmaf(x.y, u.y, acc[k]);
            acc[k] = fmaf(x.z, u.z, acc[k]);
            acc[k] = fmaf(x.w, u.w, acc[k]);
        }
    }
#pragma unroll
    for (int k = 0; k < NK; k++)
        for (int s = 16; s; s >>= 1) acc[k] += __shfl_xor_sync(0xffffffffu, acc[k], s);

    if (lane == 0) {
        float* pr = g_proj + ((size_t)v * NN + n) * YP;
#pragma unroll
        for (int k = 0; k < NK; k++) pr[k] = acc[k];
    }
}

// ---------------- kernel 2: Y_ms[v,n,:] += L_v[n, ms-range] @ z[ms-range,:] ----------------
// 384 threads, 12 warps, RPW=8, LDG.128, depth-1 ping-pong (no buffer copies).
// One z fill per tile (2048 m), zero mid-tile barriers.
#define HALF_STEP(CONS, PRE, IT)                                                   \
    do {                                                                           \
        int it_ = (IT);                                                            \
        if (it_ + 1 < STEPS) {                                                     \
            _Pragma("unroll")                                                      \
            for (int r = 0; r < RPW; r++)                                          \
                PRE[r] = __ldcs(Lt + (size_t)r * ROW4 + (it_ + 1) * 32 + lane);    \
        }                                                                          \
        int mi_ = it_ * 32 + lane;                                                 \
        _Pragma("unroll")                                                          \
        for (int q = 0; q < 4; q++) {                                              \
            unsigned long long zq[5];                                              \
            _Pragma("unroll")                                                      \
            for (int p = 0; p < 5; p++) zq[p] = zt[(q * 5 + p) * MQP + mi_];       \
            _Pragma("unroll")                                                      \
            for (int r = 0; r < RPW; r++) {                                        \
                float av_ = (q == 0) ? CONS[r].x : (q == 1) ? CONS[r].y            \
                           : (q == 2) ? CONS[r].z : CONS[r].w;                     \
                unsigned long long d_ = pack2(av_, av_);                           \
                _Pragma("unroll")                                                  \
                for (int p = 0; p < 5; p++) ffma2(acc[r][p], d_, zq[p]);           \
            }                                                                      \
        }                                                                          \
    } while (0)

__global__ __launch_bounds__(GEMV_THREADS) void gemv_kernel(const float* __restrict__ lap,
                                                            const float* __restrict__ z_ext,
                                                            int use_ext) {
    const float* zsrc = use_ext ? z_ext : g_z;
    const int zstr = use_ext ? NK : YP;
    extern __shared__ unsigned long long zt[];   // 4*5*MQP u64 = 82,560 B

    int tid = threadIdx.x, lane = tid & 31, wid = tid >> 5;
    int bx = blockIdx.x;
    int ms = bx / (NV * NRT);
    int rem = bx % (NV * NRT);
    int v = rem / NRT;
    int rt = rem % NRT;
    int n0 = rt * ROWS_PER_BLOCK + wid * RPW;

    const int ROW4 = NN / 4;
    const float4* Lt = (const float4*)(lap + ((size_t)v * NN + n0) * (size_t)NN) + ms * (M_CHUNK / 4);

    // z fill for this tile's m range
    for (int i = tid; i < 5 * M_CHUNK; i += GEMV_THREADS) {
        int p = i >> 11;                  // 0..4
        int j = i & (M_CHUNK - 1);
        const float2* zp2 = (const float2*)(zsrc + (size_t)(ms * M_CHUNK + j) * zstr + 2 * p);
        float2 zv = *zp2;
        zt[((j & 3) * 5 + p) * MQP + (j >> 2)] = pack2(zv.x, zv.y);
    }

    unsigned long long acc[RPW][5];
#pragma unroll
    for (int r = 0; r < RPW; r++)
#pragma unroll
        for (int p = 0; p < 5; p++) acc[r][p] = 0ull;

    float4 a[RPW], b[RPW];
#pragma unroll
    for (int r = 0; r < RPW; r++) a[r] = __ldcs(Lt + (size_t)r * ROW4 + lane);

    __syncthreads();

#pragma unroll 1
    for (int it2 = 0; it2 < STEPS / 2; it2++) {
        HALF_STEP(a, b, it2 * 2);
        HALF_STEP(b, a, it2 * 2 + 1);
    }

    // epilogue: packed butterfly reduce, lane 0 stores Y partial
#pragma unroll
    for (int r = 0; r < RPW; r++) {
#pragma unroll
        for (int p = 0; p < 5; p++) {
            unsigned long long vv = acc[r][p];
#pragma unroll
            for (int s = 16; s; s >>= 1) {
                unsigned long long o = __shfl_xor_sync(0xffffffffu, vv, s);
                fadd2(vv, o);
            }
            acc[r][p] = vv;
        }
        if (lane == 0) {
            float* yr = g_Y + (((size_t)ms * NV + v) * NN + n0 + r) * YP;
#pragma unroll
            for (int p = 0; p < 5; p++) {
                float2 f = unpack2(acc[r][p]);
                yr[2 * p] = f.x;
                yr[2 * p + 1] = f.y;
            }
        }
    }
}

// ---------------- kernel 3: fused combine + BN + SELU ----------------
__device__ __forceinline__ float softplusf(float x) {
    return fmaxf(x, 0.0f) + __logf(1.0f + __expf(-fabsf(x)));
}

__device__ __forceinline__ void ds_comb(float* a1, const float* a2) {
    float S1 = 0.0f, S2 = 0.0f;
#pragma unroll
    for (int k = 0; k < NK; k++) { S1 += a1[k]; S2 += a2[k]; }
    float i1 = 1.0f / S1, i2 = 1.0f / S2;
    float u1 = (float)NK * i1, u2 = (float)NK * i2;
    float b1[NK], b2[NK];
    float sb1 = 0.0f, sb2 = 0.0f, dot = 0.0f;
#pragma unroll
    for (int k = 0; k < NK; k++) {
        b1[k] = (a1[k] - 1.0f) * i1;
        b2[k] = (a2[k] - 1.0f) * i2;
        sb1 += b1[k];
        sb2 += b2[k];
        dot += b1[k] * b2[k];
    }
    float C = sb1 * sb2 - dot;
    float invd = 1.0f / (1.0f - C);
    float Sn = (float)NK * (1.0f - C) / (u1 * u2);
#pragma unroll
    for (int k = 0; k < NK; k++)
        a1[k] = (b1[k] * b2[k] + b1[k] * u2 + b2[k] * u1) * invd * Sn + 1.0f;
}

__device__ __forceinline__ float seluf(float x) {
    const float sc = 1.0507009873554805f, al = 1.6732632423543772f;
    return x > 0.0f ? sc * x : sc * al * (__expf(x) - 1.0f);
}

#define CMB_THREADS 64
#define CMB_BLOCKS (NN / CMB_THREADS)   // 96 <= 148 -> co-resident, spin safe
__global__ __launch_bounds__(CMB_THREADS) void combine_bn_kernel(const float* __restrict__ z_ext,
                                                                 int use_ext, int t,
                                                                 float* __restrict__ out,
                                                                 const float* __restrict__ gamma,
                                                                 const float* __restrict__ beta,
                                                                 const float* __restrict__ theta) {
    const float* zsrc = use_ext ? z_ext : g_z;
    const int zstr = use_ext ? NK : YP;
    int n = blockIdx.x * CMB_THREADS + threadIdx.x;
    int lane = threadIdx.x & 31;

    float zn[NK];
#pragma unroll
    for (int p = 0; p < 5; p++) {
        float2 zv = *(const float2*)(zsrc + (size_t)n * zstr + 2 * p);
        zn[2 * p] = zv.x;
        zn[2 * p + 1] = zv.y;
    }

    float ac[NK];
#pragma unroll
    for (int v = 0; v < NV; v++) {
        float yv[12], pv[12];
        const float4* p4 = (const float4*)(g_proj + ((size_t)v * NN + n) * YP);
#pragma unroll
        for (int q = 0; q < 3; q++) {
            float4 pq = p4[q];
            pv[4 * q] = pq.x; pv[4 * q + 1] = pq.y; pv[4 * q + 2] = pq.z; pv[4 * q + 3] = pq.w;
            yv[4 * q] = 0.0f; yv[4 * q + 1] = 0.0f; yv[4 * q + 2] = 0.0f; yv[4 * q + 3] = 0.0f;
        }
#pragma unroll
        for (int s = 0; s < MSPLIT; s++) {
            const float4* y4 = (const float4*)(g_Y + (((size_t)s * NV + v) * NN + n) * YP);
#pragma unroll
            for (int q = 0; q < 3; q++) {
                float4 yq = y4[q];
                yv[4 * q] += yq.x; yv[4 * q + 1] += yq.y; yv[4 * q + 2] += yq.z; yv[4 * q + 3] += yq.w;
            }
        }
        float av[NK];
#pragma unroll
        for (int k = 0; k < NK; k++) av[k] = softplusf(zn[k] - yv[k] + pv[k]) + 1.0f;
        if (v == 0) {
#pragma unroll
            for (int k = 0; k < NK; k++) ac[k] = av[k];
        } else {
            ds_comb(ac, av);
        }
    }

    float rs[NK], rq[NK];
#pragma unroll
    for (int k = 0; k < NK; k++) { rs[k] = ac[k]; rq[k] = ac[k] * ac[k]; }
#pragma unroll
    for (int k = 0; k < NK; k++) {
        for (int s = 16; s; s >>= 1) {
            rs[k] += __shfl_xor_sync(0xffffffffu, rs[k], s);
            rq[k] += __shfl_xor_sync(0xffffffffu, rq[k], s);
        }
    }
    __shared__ float sh[2 * NK];
    if (threadIdx.x < 2 * NK) sh[threadIdx.x] = 0.0f;
    __syncthreads();
    if (lane == 0) {
#pragma unroll
        for (int k = 0; k < NK; k++) {
            atomicAdd(&sh[k], rs[k]);
            atomicAdd(&sh[NK + k], rq[k]);
        }
    }
    __syncthreads();
    if (threadIdx.x < 2 * NK)
        atomicAdd(&g_stats[t * 2 * NK + threadIdx.x], sh[threadIdx.x]);

    __threadfence();
    __syncthreads();
    if (threadIdx.x == 0) {
        atomicAdd(&g_cnt[t], 1);
        while (atomicAdd(&g_cnt[t], 0) < CMB_BLOCKS) { __nanosleep(64); }
    }
    __syncthreads();
    __threadfence();

    float th = theta[0];
#pragma unroll
    for (int k = 0; k < NK; k++) {
        float mu = g_stats[t * 2 * NK + k] * (1.0f / NN);
        float ms = g_stats[t * 2 * NK + NK + k] * (1.0f / NN);
        float var = ms - mu * mu;
        float inv = rsqrtf(var + BN_EPS);
        float hn = (ac[k] - mu) * inv * gamma[k] + beta[k];
        float zz = seluf(hn - th) - seluf(-hn - th);
        out[(size_t)t * NN * NK + (size_t)n * NK + k] = zz;
        g_z[(size_t)n * YP + k] = zz;
    }
}

// ---------------- launcher ----------------
extern "C" void kernel_launch(void* const* d_in, const int* in_sizes, int n_in,
                              void* d_out, int out_size) {
    (void)in_sizes; (void)n_in; (void)out_size;
    const float* feat  = (const float*)d_in[0];
    const float* lap   = (const float*)d_in[1];
    const float* z0    = (const float*)d_in[2];
    const float* U     = (const float*)d_in[3];
    const float* theta = (const float*)d_in[4];
    const float* gamma = (const float*)d_in[5];
    const float* beta  = (const float*)d_in[6];
    float* out = (float*)d_out;

    const int ZT_BYTES = 4 * 5 * MQP * 8;   // 82,560 B dynamic smem
    static int configured = 0;
    if (!configured) {
        cudaFuncSetAttribute(gemv_kernel, cudaFuncAttributeMaxDynamicSharedMemorySize, ZT_BYTES);
        configured = 1;
    }

    proj_kernel<<<NV * (NN / 8), 256>>>(feat, U);

    for (int t = 0; t < NITERS; t++) {
        int use_ext = (t == 0) ? 1 : 0;
        gemv_kernel<<<NTILES, GEMV_THREADS, ZT_BYTES>>>(lap, z0, use_ext);
        combine_bn_kernel<<<CMB_BLOCKS, CMB_THREADS>>>(z0, use_ext, t, out, gamma, beta, theta);
    }
}

// round 13
// speedup vs baseline: 4.0312x; 1.0384x over previous
#include <cuda_runtime.h>
#include <stdint.h>
#include <math.h>

#define NN 6144
#define NV 3
#define NK 10
#define NF 512
#define YP 12
#define NITERS 2
#define BN_EPS 1e-5f

#define MSPLIT 3
#define M_CHUNK 2048                   // m per tile (one fill)
#define MQP 516                        // 512 + pad (u64 row stride)
#define STEPS 16                       // 2048 / 128
#define ZSLICE (4 * 5 * MQP)           // 10320 u64 per m-slice (82,560 B)

#define GEMV_THREADS 384               // 12 warps -> reg cap 170
#define RPW 8
#define ROWS_PER_BLOCK 96              // 12 warps * 8 rows
#define NRT (NN / ROWS_PER_BLOCK)      // 64 row-tiles per view
#define NTILES (MSPLIT * NV * NRT)     // 576

// ---------------- scratch ----------------
__device__ float g_proj[NV * NN * YP];
__device__ float g_Y[MSPLIT * NV * NN * YP];   // m-split partials
__device__ float g_z[NN * YP];
__device__ __align__(16) unsigned long long g_zpack[MSPLIT][ZSLICE];
__device__ float g_stats[NITERS * 2 * NK];
__device__ int   g_cnt[NITERS];

// ---------------- packed f32x2 helpers ----------------
__device__ __forceinline__ unsigned long long pack2(float a, float b) {
    unsigned long long r;
    asm("mov.b64 %0, {%1, %2};" : "=l"(r) : "f"(a), "f"(b));
    return r;
}
__device__ __forceinline__ void ffma2(unsigned long long& d, unsigned long long a, unsigned long long b) {
    asm("fma.rn.f32x2 %0, %1, %2, %0;" : "+l"(d) : "l"(a), "l"(b));
}
__device__ __forceinline__ void fadd2(unsigned long long& d, unsigned long long a) {
    asm("add.rn.f32x2 %0, %0, %1;" : "+l"(d) : "l"(a));
}
__device__ __forceinline__ float2 unpack2(unsigned long long v) {
    float2 r;
    asm("mov.b64 {%0, %1}, %2;" : "=f"(r.x), "=f"(r.y) : "l"(v));
    return r;
}
__device__ __forceinline__ void cp_async16(void* smem_dst, const void* gmem_src) {
    unsigned int s = (unsigned int)__cvta_generic_to_shared(smem_dst);
    asm volatile("cp.async.cg.shared.global [%0], [%1], 16;" :: "r"(s), "l"(gmem_src));
}

// zpack float index for (m, k): slice ms, u64 idx (q*5+p)*MQP + col, half k&1
__device__ __forceinline__ void zpack_store(int m, int k, float val) {
    int ms = m >> 11;
    int j = m & 2047;
    int idx = (((j & 3) * 5 + (k >> 1)) * MQP + (j >> 2)) * 2 + (k & 1);
    ((float*)g_zpack[ms])[idx] = val;
}

// ---------------- kernel 1: proj (also zeroes stats + counters) ----------------
__global__ __launch_bounds__(256) void proj_kernel(const float* __restrict__ feat,
                                                   const float* __restrict__ U) {
    __shared__ float Ut[NK][NF];
    int tid = threadIdx.x, lane = tid & 31, wid = tid >> 5;
    int bx = blockIdx.x;
    if (bx == 0) {
        if (tid < NITERS * 2 * NK) g_stats[tid] = 0.0f;
        if (tid >= 64 && tid < 64 + NITERS) g_cnt[tid - 64] = 0;
    }

    int v = bx / (NN / 8);
    int rb = bx % (NN / 8);

    for (int i = tid; i < NF * NK; i += 256) {
        int f = i / NK, k = i % NK;
        Ut[k][f] = U[(size_t)v * NF * NK + i];
    }
    __syncthreads();

    int n = rb * 8 + wid;
    const float4* xr = (const float4*)(feat + ((size_t)v * NN + n) * NF);
    float acc[NK];
#pragma unroll
    for (int k = 0; k < NK; k++) acc[k] = 0.0f;

#pragma unroll
    for (int it = 0; it < NF / 128; it++) {
        int f4 = it * 32 + lane;
        float4 x = xr[f4];
#pragma unroll
        for (int k = 0; k < NK; k++) {
            float4 u = *(const float4*)&Ut[k][f4 * 4];
            acc[k] = fmaf(x.x, u.x, acc[k]);
            acc[k] = fmaf(x.y, u.y, acc[k]);
            acc[k] = fmaf(x.z, u.z, acc[k]);
            acc[k] = fmaf(x.w, u.w, acc[k]);
        }
    }
#pragma unroll
    for (int k = 0; k < NK; k++)
        for (int s = 16; s; s >>= 1) acc[k] += __shfl_xor_sync(0xffffffffu, acc[k], s);

    if (lane == 0) {
        float* pr = g_proj + ((size_t)v * NN + n) * YP;
#pragma unroll
        for (int k = 0; k < NK; k++) pr[k] = acc[k];
    }
}

// ---------------- kernel 1b: pack z0 into g_zpack ----------------
__global__ __launch_bounds__(256) void zpack0_kernel(const float* __restrict__ z0) {
    int m = blockIdx.x * 256 + threadIdx.x;   // covers NN
#pragma unroll
    for (int k = 0; k < NK; k++) zpack_store(m, k, z0[(size_t)m * NK + k]);
}

// ---------------- kernel 2: Y_ms[v,n,:] = L_v[n, ms-range] @ z[ms-range,:] ----------------
#define HALF_STEP(CONS, PRE, IT)                                                   \
    do {                                                                           \
        int it_ = (IT);                                                            \
        if (it_ + 1 < STEPS) {                                                     \
            _Pragma("unroll")                                                      \
            for (int r = 0; r < RPW; r++)                                          \
                PRE[r] = __ldcs(Lt + (size_t)r * ROW4 + (it_ + 1) * 32 + lane);    \
        }                                                                          \
        int mi_ = it_ * 32 + lane;                                                 \
        _Pragma("unroll")                                                          \
        for (int q = 0; q < 4; q++) {                                              \
            unsigned long long zq[5];                                              \
            _Pragma("unroll")                                                      \
            for (int p = 0; p < 5; p++) zq[p] = zt[(q * 5 + p) * MQP + mi_];       \
            _Pragma("unroll")                                                      \
            for (int r = 0; r < RPW; r++) {                                        \
                float av_ = (q == 0) ? CONS[r].x : (q == 1) ? CONS[r].y            \
                           : (q == 2) ? CONS[r].z : CONS[r].w;                     \
                unsigned long long d_ = pack2(av_, av_);                           \
                _Pragma("unroll")                                                  \
                for (int p = 0; p < 5; p++) ffma2(acc[r][p], d_, zq[p]);           \
            }                                                                      \
        }                                                                          \
    } while (0)

__global__ __launch_bounds__(GEMV_THREADS) void gemv_kernel(const float* __restrict__ lap) {
    extern __shared__ unsigned long long zt[];   // ZSLICE u64 = 82,560 B

    int tid = threadIdx.x, lane = tid & 31, wid = tid >> 5;
    int bx = blockIdx.x;
    int ms = bx / (NV * NRT);
    int rem = bx % (NV * NRT);
    int v = rem / NRT;
    int rt = rem % NRT;
    int n0 = rt * ROWS_PER_BLOCK + wid * RPW;

    const int ROW4 = NN / 4;
    const float4* Lt = (const float4*)(lap + ((size_t)v * NN + n0) * (size_t)NN) + ms * (M_CHUNK / 4);

    // z fill: contiguous cp.async copy from pre-packed global (no registers, no chains)
    {
        const char* src = (const char*)g_zpack[ms];
        char* dst = (char*)zt;
#pragma unroll 1
        for (int i = tid; i < ZSLICE / 2; i += GEMV_THREADS)   // 5160 uint4
            cp_async16(dst + (size_t)i * 16, src + (size_t)i * 16);
        asm volatile("cp.async.commit_group;");
    }

    unsigned long long acc[RPW][5];
#pragma unroll
    for (int r = 0; r < RPW; r++)
#pragma unroll
        for (int p = 0; p < 5; p++) acc[r][p] = 0ull;

    float4 a[RPW], b[RPW];
#pragma unroll
    for (int r = 0; r < RPW; r++) a[r] = __ldcs(Lt + (size_t)r * ROW4 + lane);

    asm volatile("cp.async.wait_group 0;");
    __syncthreads();

#pragma unroll 1
    for (int it2 = 0; it2 < STEPS / 2; it2++) {
        HALF_STEP(a, b, it2 * 2);
        HALF_STEP(b, a, it2 * 2 + 1);
    }

    // epilogue: packed butterfly reduce, lane 0 stores Y partial
#pragma unroll
    for (int r = 0; r < RPW; r++) {
#pragma unroll
        for (int p = 0; p < 5; p++) {
            unsigned long long vv = acc[r][p];
#pragma unroll
            for (int s = 16; s; s >>= 1) {
                unsigned long long o = __shfl_xor_sync(0xffffffffu, vv, s);
                fadd2(vv, o);
            }
            acc[r][p] = vv;
        }
        if (lane == 0) {
            float* yr = g_Y + (((size_t)ms * NV + v) * NN + n0 + r) * YP;
#pragma unroll
            for (int p = 0; p < 5; p++) {
                float2 f = unpack2(acc[r][p]);
                yr[2 * p] = f.x;
                yr[2 * p + 1] = f.y;
            }
        }
    }
}

// ---------------- kernel 3: fused combine + BN + SELU (+ zpack for next iter) ----------------
__device__ __forceinline__ float softplusf(float x) {
    return fmaxf(x, 0.0f) + __logf(1.0f + __expf(-fabsf(x)));
}

__device__ __forceinline__ void ds_comb(float* a1, const float* a2) {
    float S1 = 0.0f, S2 = 0.0f;
#pragma unroll
    for (int k = 0; k < NK; k++) { S1 += a1[k]; S2 += a2[k]; }
    float i1 = 1.0f / S1, i2 = 1.0f / S2;
    float u1 = (float)NK * i1, u2 = (float)NK * i2;
    float b1[NK], b2[NK];
    float sb1 = 0.0f, sb2 = 0.0f, dot = 0.0f;
#pragma unroll
    for (int k = 0; k < NK; k++) {
        b1[k] = (a1[k] - 1.0f) * i1;
        b2[k] = (a2[k] - 1.0f) * i2;
        sb1 += b1[k];
        sb2 += b2[k];
        dot += b1[k] * b2[k];
    }
    float C = sb1 * sb2 - dot;
    float invd = 1.0f / (1.0f - C);
    float Sn = (float)NK * (1.0f - C) / (u1 * u2);
#pragma unroll
    for (int k = 0; k < NK; k++)
        a1[k] = (b1[k] * b2[k] + b1[k] * u2 + b2[k] * u1) * invd * Sn + 1.0f;
}

__device__ __forceinline__ float seluf(float x) {
    const float sc = 1.0507009873554805f, al = 1.6732632423543772f;
    return x > 0.0f ? sc * x : sc * al * (__expf(x) - 1.0f);
}

#define CMB_THREADS 64
#define CMB_BLOCKS (NN / CMB_THREADS)   // 96 <= 148 -> co-resident, spin safe
__global__ __launch_bounds__(CMB_THREADS) void combine_bn_kernel(const float* __restrict__ z_ext,
                                                                 int use_ext, int t, int last,
                                                                 float* __restrict__ out,
                                                                 const float* __restrict__ gamma,
                                                                 const float* __restrict__ beta,
                                                                 const float* __restrict__ theta) {
    const float* zsrc = use_ext ? z_ext : g_z;
    const int zstr = use_ext ? NK : YP;
    int n = blockIdx.x * CMB_THREADS + threadIdx.x;
    int lane = threadIdx.x & 31;

    float zn[NK];
#pragma unroll
    for (int p = 0; p < 5; p++) {
        float2 zv = *(const float2*)(zsrc + (size_t)n * zstr + 2 * p);
        zn[2 * p] = zv.x;
        zn[2 * p + 1] = zv.y;
    }

    float ac[NK];
#pragma unroll
    for (int v = 0; v < NV; v++) {
        float yv[12], pv[12];
        const float4* p4 = (const float4*)(g_proj + ((size_t)v * NN + n) * YP);
#pragma unroll
        for (int q = 0; q < 3; q++) {
            float4 pq = p4[q];
            pv[4 * q] = pq.x; pv[4 * q + 1] = pq.y; pv[4 * q + 2] = pq.z; pv[4 * q + 3] = pq.w;
            yv[4 * q] = 0.0f; yv[4 * q + 1] = 0.0f; yv[4 * q + 2] = 0.0f; yv[4 * q + 3] = 0.0f;
        }
#pragma unroll
        for (int s = 0; s < MSPLIT; s++) {
            const float4* y4 = (const float4*)(g_Y + (((size_t)s * NV + v) * NN + n) * YP);
#pragma unroll
            for (int q = 0; q < 3; q++) {
                float4 yq = y4[q];
                yv[4 * q] += yq.x; yv[4 * q + 1] += yq.y; yv[4 * q + 2] += yq.z; yv[4 * q + 3] += yq.w;
            }
        }
        float av[NK];
#pragma unroll
        for (int k = 0; k < NK; k++) av[k] = softplusf(zn[k] - yv[k] + pv[k]) + 1.0f;
        if (v == 0) {
#pragma unroll
            for (int k = 0; k < NK; k++) ac[k] = av[k];
        } else {
            ds_comb(ac, av);
        }
    }

    float rs[NK], rq[NK];
#pragma unroll
    for (int k = 0; k < NK; k++) { rs[k] = ac[k]; rq[k] = ac[k] * ac[k]; }
#pragma unroll
    for (int k = 0; k < NK; k++) {
        for (int s = 16; s; s >>= 1) {
            rs[k] += __shfl_xor_sync(0xffffffffu, rs[k], s);
            rq[k] += __shfl_xor_sync(0xffffffffu, rq[k], s);
        }
    }
    __shared__ float sh[2 * NK];
    if (threadIdx.x < 2 * NK) sh[threadIdx.x] = 0.0f;
    __syncthreads();
    if (lane == 0) {
#pragma unroll
        for (int k = 0; k < NK; k++) {
            atomicAdd(&sh[k], rs[k]);
            atomicAdd(&sh[NK + k], rq[k]);
        }
    }
    __syncthreads();
    if (threadIdx.x < 2 * NK)
        atomicAdd(&g_stats[t * 2 * NK + threadIdx.x], sh[threadIdx.x]);

    __threadfence();
    __syncthreads();
    if (threadIdx.x == 0) {
        atomicAdd(&g_cnt[t], 1);
        while (atomicAdd(&g_cnt[t], 0) < CMB_BLOCKS) { __nanosleep(64); }
    }
    __syncthreads();
    __threadfence();

    float th = theta[0];
#pragma unroll
    for (int k = 0; k < NK; k++) {
        float mu = g_stats[t * 2 * NK + k] * (1.0f / NN);
        float ms = g_stats[t * 2 * NK + NK + k] * (1.0f / NN);
        float var = ms - mu * mu;
        float inv = rsqrtf(var + BN_EPS);
        float hn = (ac[k] - mu) * inv * gamma[k] + beta[k];
        float zz = seluf(hn - th) - seluf(-hn - th);
        out[(size_t)t * NN * NK + (size_t)n * NK + k] = zz;
        if (!last) {
            g_z[(size_t)n * YP + k] = zz;
            zpack_store(n, k, zz);
        }
    }
}

// ---------------- launcher ----------------
extern "C" void kernel_launch(void* const* d_in, const int* in_sizes, int n_in,
                              void* d_out, int out_size) {
    (void)in_sizes; (void)n_in; (void)out_size;
    const float* feat  = (const float*)d_in[0];
    const float* lap   = (const float*)d_in[1];
    const float* z0    = (const float*)d_in[2];
    const float* U     = (const float*)d_in[3];
    const float* theta = (const float*)d_in[4];
    const float* gamma = (const float*)d_in[5];
    const float* beta  = (const float*)d_in[6];
    float* out = (float*)d_out;

    const int ZT_BYTES = ZSLICE * 8;   // 82,560 B dynamic smem
    static int configured = 0;
    if (!configured) {
        cudaFuncSetAttribute(gemv_kernel, cudaFuncAttributeMaxDynamicSharedMemorySize, ZT_BYTES);
        configured = 1;
    }

    proj_kernel<<<NV * (NN / 8), 256>>>(feat, U);
    zpack0_kernel<<<NN / 256, 256>>>(z0);

    for (int t = 0; t < NITERS; t++) {
        int use_ext = (t == 0) ? 1 : 0;
        gemv_kernel<<<NTILES, GEMV_THREADS, ZT_BYTES>>>(lap);
        combine_bn_kernel<<<CMB_BLOCKS, CMB_THREADS>>>(z0, use_ext, t, t == NITERS - 1,
                                                       out, gamma, beta, theta);
    }
}